// round 2
// baseline (speedup 1.0000x reference)
#include <cuda_runtime.h>
#include <cuda_bf16.h>
#include <cstdint>

#define DIM 1024
#define NGROUPS 32
#define GSIZE 32
#define TT 1024
#define BB 16
#define MROWS (TT * BB)          // 16384
#define BD (BB * DIM)            // 16384

// ---------------- scratch (device globals; no allocation allowed) ----------------
__device__ float g_vx[MROWS * DIM];
__device__ float g_alpha[MROWS * DIM];
__device__ float g_delta[MROWS * DIM];
__device__ float g_compete[MROWS * DIM];

// ---------------- helpers ----------------
__device__ __forceinline__ uint32_t f2tf32(float x) {
    uint32_t r;
    asm("cvt.rna.tf32.f32 %0, %1;" : "=r"(r) : "f"(x));
    return r;
}

__device__ __forceinline__ void mma_tf32(float* c, const uint32_t* a, const uint32_t* b) {
    asm volatile(
        "mma.sync.aligned.m16n8k8.row.col.f32.tf32.tf32.f32 "
        "{%0,%1,%2,%3}, {%4,%5,%6,%7}, {%8,%9}, {%0,%1,%2,%3};"
        : "+f"(c[0]), "+f"(c[1]), "+f"(c[2]), "+f"(c[3])
        : "r"(a[0]), "r"(a[1]), "r"(a[2]), "r"(a[3]), "r"(b[0]), "r"(b[1]));
}

// ---------------- GEMM: C[M,N] = A[M,K] @ W[N,K]^T, double-buffered ----------------
// fused=1: blockIdx.x in [0,24): wsel = x>>3 selects (W,bias,C,mode 0/1/2)
//   mode 0: y = acc + bias[col]
//   mode 1: y = 1 + softplus(acc + bias[col])
//   mode 2: y = sigmoid(acc + bias[col])
// fused=0: mode 3: y = compete[row*N+col] * silu(acc)
#define BM 128
#define BN 128
#define BK 16
#define PAD 4

__global__ void __launch_bounds__(256, 2)
gemm_tf32_kernel(const float* __restrict__ A,
                 const float* __restrict__ W0, const float* __restrict__ W1,
                 const float* __restrict__ W2,
                 const float* __restrict__ bias0, const float* __restrict__ bias1,
                 const float* __restrict__ bias2,
                 const float* __restrict__ comp,
                 float* __restrict__ C0, float* __restrict__ C1, float* __restrict__ C2,
                 int fused)
{
    __shared__ uint32_t As[2][BM][BK + PAD];
    __shared__ uint32_t Bs[2][BN][BK + PAD];

    const int K = DIM, N = DIM;

    int mode, ntile;
    const float* W;
    const float* bias;
    float* C;
    if (fused) {
        int wsel = blockIdx.x >> 3;
        ntile = blockIdx.x & 7;
        mode = wsel;
        W    = (wsel == 0) ? W0 : ((wsel == 1) ? W1 : W2);
        bias = (wsel == 0) ? bias0 : ((wsel == 1) ? bias1 : bias2);
        C    = (wsel == 0) ? C0 : ((wsel == 1) ? C1 : C2);
    } else {
        mode = 3; ntile = blockIdx.x; W = W0; bias = bias0; C = C0;
    }

    const int tid  = threadIdx.x;
    const int lane = tid & 31;
    const int warp = tid >> 5;
    const int warpM = warp >> 2;   // 0..1
    const int warpN = warp & 3;    // 0..3
    const int wmBase = warpM * 64;
    const int wnBase = warpN * 32;

    const int m0 = blockIdx.y * BM;
    const int n0 = ntile * BN;

    const int ldRow = tid >> 2;
    const int ldCol = (tid & 3) * 4;

    const float* Aptr  = A + (size_t)(m0 + ldRow) * K + ldCol;
    const float* Aptr2 = Aptr + (size_t)64 * K;
    const float* Wptr  = W + (size_t)(n0 + ldRow) * K + ldCol;
    const float* Wptr2 = Wptr + (size_t)64 * K;

    float acc[4][4][4];
#pragma unroll
    for (int i = 0; i < 4; i++)
#pragma unroll
        for (int j = 0; j < 4; j++)
#pragma unroll
            for (int r = 0; r < 4; r++) acc[i][j][r] = 0.f;

    const int grp = lane >> 2;   // 0..7
    const int tig = lane & 3;    // 0..3

    // prologue: stage k0=0 into buffer 0
    float4 ra0 = *(const float4*)(Aptr);
    float4 ra1 = *(const float4*)(Aptr2);
    float4 rb0 = *(const float4*)(Wptr);
    float4 rb1 = *(const float4*)(Wptr2);
    {
        As[0][ldRow][ldCol + 0] = f2tf32(ra0.x); As[0][ldRow][ldCol + 1] = f2tf32(ra0.y);
        As[0][ldRow][ldCol + 2] = f2tf32(ra0.z); As[0][ldRow][ldCol + 3] = f2tf32(ra0.w);
        As[0][ldRow + 64][ldCol + 0] = f2tf32(ra1.x); As[0][ldRow + 64][ldCol + 1] = f2tf32(ra1.y);
        As[0][ldRow + 64][ldCol + 2] = f2tf32(ra1.z); As[0][ldRow + 64][ldCol + 3] = f2tf32(ra1.w);
        Bs[0][ldRow][ldCol + 0] = f2tf32(rb0.x); Bs[0][ldRow][ldCol + 1] = f2tf32(rb0.y);
        Bs[0][ldRow][ldCol + 2] = f2tf32(rb0.z); Bs[0][ldRow][ldCol + 3] = f2tf32(rb0.w);
        Bs[0][ldRow + 64][ldCol + 0] = f2tf32(rb1.x); Bs[0][ldRow + 64][ldCol + 1] = f2tf32(rb1.y);
        Bs[0][ldRow + 64][ldCol + 2] = f2tf32(rb1.z); Bs[0][ldRow + 64][ldCol + 3] = f2tf32(rb1.w);
    }
    __syncthreads();

    int cur = 0;
    for (int k0 = 0; k0 < K; k0 += BK) {
        const bool has_next = (k0 + BK) < K;
        if (has_next) {
            int kn = k0 + BK;
            ra0 = *(const float4*)(Aptr  + kn);
            ra1 = *(const float4*)(Aptr2 + kn);
            rb0 = *(const float4*)(Wptr  + kn);
            rb1 = *(const float4*)(Wptr2 + kn);
        }

        // compute on buffer `cur`
#pragma unroll
        for (int kk = 0; kk < BK; kk += 8) {
            uint32_t af[4][4];
#pragma unroll
            for (int mt = 0; mt < 4; mt++) {
                int r = wmBase + mt * 16 + grp;
                af[mt][0] = As[cur][r][kk + tig];
                af[mt][1] = As[cur][r + 8][kk + tig];
                af[mt][2] = As[cur][r][kk + tig + 4];
                af[mt][3] = As[cur][r + 8][kk + tig + 4];
            }
            uint32_t bf[4][2];
#pragma unroll
            for (int nt = 0; nt < 4; nt++) {
                int n = wnBase + nt * 8 + grp;
                bf[nt][0] = Bs[cur][n][kk + tig];
                bf[nt][1] = Bs[cur][n][kk + tig + 4];
            }
#pragma unroll
            for (int mt = 0; mt < 4; mt++)
#pragma unroll
                for (int nt = 0; nt < 4; nt++)
                    mma_tf32(acc[mt][nt], af[mt], bf[nt]);
        }

        if (has_next) {
            int nxt = cur ^ 1;
            As[nxt][ldRow][ldCol + 0] = f2tf32(ra0.x); As[nxt][ldRow][ldCol + 1] = f2tf32(ra0.y);
            As[nxt][ldRow][ldCol + 2] = f2tf32(ra0.z); As[nxt][ldRow][ldCol + 3] = f2tf32(ra0.w);
            As[nxt][ldRow + 64][ldCol + 0] = f2tf32(ra1.x); As[nxt][ldRow + 64][ldCol + 1] = f2tf32(ra1.y);
            As[nxt][ldRow + 64][ldCol + 2] = f2tf32(ra1.z); As[nxt][ldRow + 64][ldCol + 3] = f2tf32(ra1.w);
            Bs[nxt][ldRow][ldCol + 0] = f2tf32(rb0.x); Bs[nxt][ldRow][ldCol + 1] = f2tf32(rb0.y);
            Bs[nxt][ldRow][ldCol + 2] = f2tf32(rb0.z); Bs[nxt][ldRow][ldCol + 3] = f2tf32(rb0.w);
            Bs[nxt][ldRow + 64][ldCol + 0] = f2tf32(rb1.x); Bs[nxt][ldRow + 64][ldCol + 1] = f2tf32(rb1.y);
            Bs[nxt][ldRow + 64][ldCol + 2] = f2tf32(rb1.z); Bs[nxt][ldRow + 64][ldCol + 3] = f2tf32(rb1.w);
        }
        __syncthreads();
        cur ^= 1;
    }

    // epilogue (float2 stores: r pairs are adjacent columns)
#pragma unroll
    for (int mt = 0; mt < 4; mt++) {
#pragma unroll
        for (int nt = 0; nt < 4; nt++) {
#pragma unroll
            for (int half = 0; half < 2; half++) {
                int row = m0 + wmBase + mt * 16 + grp + half * 8;
                int col = n0 + wnBase + nt * 8 + 2 * tig;
                float v0 = acc[mt][nt][half * 2 + 0];
                float v1 = acc[mt][nt][half * 2 + 1];
                float y0, y1;
                if (mode == 0) {
                    y0 = v0 + bias[col]; y1 = v1 + bias[col + 1];
                } else if (mode == 1) {
                    float x0 = v0 + bias[col], x1 = v1 + bias[col + 1];
                    y0 = 1.0f + ((x0 > 20.f) ? x0 : log1pf(__expf(x0)));
                    y1 = 1.0f + ((x1 > 20.f) ? x1 : log1pf(__expf(x1)));
                } else if (mode == 2) {
                    float x0 = v0 + bias[col], x1 = v1 + bias[col + 1];
                    y0 = 1.0f / (1.0f + __expf(-x0));
                    y1 = 1.0f / (1.0f + __expf(-x1));
                } else {
                    float s0 = v0 / (1.0f + __expf(-v0));
                    float s1 = v1 / (1.0f + __expf(-v1));
                    const float2 cc = *(const float2*)(comp + (size_t)row * N + col);
                    y0 = cc.x * s0; y1 = cc.y * s1;
                }
                float2 o; o.x = y0; o.y = y1;
                *(float2*)(C + (size_t)row * N + col) = o;
            }
        }
    }
}

// ---------------- sequential scan (elementwise recurrence only) ----------------
// 128 blocks x 128 threads -> spread over >=128 SMs. One thread per (b,d).
__global__ void __launch_bounds__(128)
scan_kernel(const float* __restrict__ vx, const float* __restrict__ alpha,
            const float* __restrict__ delta, const float* __restrict__ h0,
            const float* __restrict__ r_h, float* __restrict__ out_h)
{
    int gtid = blockIdx.x * 128 + threadIdx.x;   // 0..16383
    int b = gtid >> 10;            // /DIM
    int d = gtid & 1023;
    size_t base = (size_t)b * DIM + d;

    float rh = r_h[d];
    float h = h0[base];
    out_h[base] = h;               // h[0] = h0

    const int S = BD;              // stride per timestep
    float pvx[8], pal[8], pdl[8];
#pragma unroll
    for (int i = 0; i < 8; i++) {
        size_t off = (size_t)i * S + base;
        pvx[i] = __ldcs(vx + off);
        pal[i] = __ldcs(alpha + off);
        pdl[i] = __ldcs(delta + off);
    }

    for (int t0 = 0; t0 < TT; t0 += 8) {
#pragma unroll
        for (int i = 0; i < 8; i++) {
            int t = t0 + i;
            float vv = pvx[i], aa = pal[i], dd = pdl[i];
            int tn = t + 8;
            if (tn < TT) {
                size_t off = (size_t)tn * S + base;
                pvx[i] = __ldcs(vx + off);
                pal[i] = __ldcs(alpha + off);
                pdl[i] = __ldcs(delta + off);
            }
            float v = vv + rh * h;
            float av = fminf(fmaxf(fabsf(v), 1e-6f), 10.0f);
            float cand = __powf(av, aa);
            cand = (v >= 0.f) ? cand : -cand;
            if (v == 0.f) cand = 0.f;     // jnp.sign(0) == 0
            h = h + dd * (cand - h);
            out_h[(size_t)(t + 1) * S + base] = h;
        }
    }
}

// ---------------- compete = group softmax over h[1:], fully parallel ----------------
__global__ void __launch_bounds__(256)
compete_kernel(const float* __restrict__ h, float* __restrict__ comp)
{
    size_t idx = (size_t)blockIdx.x * blockDim.x + threadIdx.x;
    float v = h[idx];
    float m = v;
#pragma unroll
    for (int o = 16; o > 0; o >>= 1) m = fmaxf(m, __shfl_xor_sync(0xffffffffu, m, o));
    float e = __expf(v - m);
    float s = e;
#pragma unroll
    for (int o = 16; o > 0; o >>= 1) s += __shfl_xor_sync(0xffffffffu, s, o);
    comp[idx] = e / s;
}

// ---------------- launch ----------------
extern "C" void kernel_launch(void* const* d_in, const int* in_sizes, int n_in,
                              void* d_out, int out_size)
{
    const float* x       = (const float*)d_in[0];   // [T,B,D]
    const float* h0      = (const float*)d_in[1];   // [B,D]
    const float* W_x     = (const float*)d_in[2];   // [D,D]
    const float* r_h     = (const float*)d_in[3];   // [D]
    const float* b       = (const float*)d_in[4];   // [D]
    const float* W_alpha = (const float*)d_in[5];
    const float* b_alpha = (const float*)d_in[6];
    const float* W_delta = (const float*)d_in[7];
    const float* b_delta = (const float*)d_in[8];
    const float* W_out   = (const float*)d_in[9];

    float* out = (float*)d_out;
    float* out_h = out;                                  // [T+1,B,D]
    float* out_y = out + (size_t)(TT + 1) * BD;          // [T,B,D]

    float *vx, *al, *dl, *cp;
    cudaGetSymbolAddress((void**)&vx, g_vx);
    cudaGetSymbolAddress((void**)&al, g_alpha);
    cudaGetSymbolAddress((void**)&dl, g_delta);
    cudaGetSymbolAddress((void**)&cp, g_compete);

    // 1) fused projections: one launch, 3 weights (A tile L2-shared across weights)
    dim3 pgrid(3 * (DIM / BN), MROWS / BM);   // (24, 128)
    gemm_tf32_kernel<<<pgrid, 256>>>(x, W_x, W_alpha, W_delta, b, b_alpha, b_delta,
                                     nullptr, vx, al, dl, 1);
    // 2) sequential scan -> h states (written straight into d_out)
    scan_kernel<<<128, 128>>>(vx, al, dl, h0, r_h, out_h);
    // 3) group softmax over h[1:]
    compete_kernel<<<(MROWS * DIM) / 256, 256>>>(out_h + BD, cp);
    // 4) output GEMM with compete*silu epilogue
    dim3 ogrid(DIM / BN, MROWS / BM);          // (8, 128)
    gemm_tf32_kernel<<<ogrid, 256>>>(out_h + BD, W_out, nullptr, nullptr,
                                     nullptr, nullptr, nullptr,
                                     cp, out_y, nullptr, nullptr, 0);
}

// round 3
// speedup vs baseline: 1.1236x; 1.1236x over previous
#include <cuda_runtime.h>
#include <cuda_bf16.h>
#include <cstdint>

#define DIM 1024
#define NGROUPS 32
#define GSIZE 32
#define TT 1024
#define BB 16
#define MROWS (TT * BB)          // 16384
#define BD (BB * DIM)            // 16384

// ---------------- scratch (device globals; no allocation allowed) ----------------
__device__ float g_vx[MROWS * DIM];
__device__ float g_alpha[MROWS * DIM];
__device__ float g_delta[MROWS * DIM];
__device__ float g_compete[MROWS * DIM];

// ---------------- helpers ----------------
__device__ __forceinline__ uint32_t f2tf32(float x) {
    uint32_t r;
    asm("cvt.rna.tf32.f32 %0, %1;" : "=r"(r) : "f"(x));
    return r;
}

__device__ __forceinline__ void mma_tf32(float* c, const uint32_t* a, const uint32_t* b) {
    asm volatile(
        "mma.sync.aligned.m16n8k8.row.col.f32.tf32.tf32.f32 "
        "{%0,%1,%2,%3}, {%4,%5,%6,%7}, {%8,%9}, {%0,%1,%2,%3};"
        : "+f"(c[0]), "+f"(c[1]), "+f"(c[2]), "+f"(c[3])
        : "r"(a[0]), "r"(a[1]), "r"(a[2]), "r"(a[3]), "r"(b[0]), "r"(b[1]));
}

__device__ __forceinline__ void ldsm_x4(uint32_t& r0, uint32_t& r1, uint32_t& r2, uint32_t& r3,
                                        uint32_t addr) {
    asm volatile("ldmatrix.sync.aligned.m8n8.x4.shared.b16 {%0,%1,%2,%3}, [%4];"
                 : "=r"(r0), "=r"(r1), "=r"(r2), "=r"(r3) : "r"(addr));
}

__device__ __forceinline__ uint32_t smem_u32(const void* p) {
    uint32_t a;
    asm("{ .reg .u64 t; cvta.to.shared.u64 t, %1; cvt.u32.u64 %0, t; }" : "=r"(a) : "l"(p));
    return a;
}

// ---------------- GEMM: C[M,N] = A[M,K] @ W[N,K]^T, double-buffered + ldmatrix ----
// fused=1: blockIdx.x in [0,24): wsel = x>>3 selects (W,bias,C,mode 0/1/2)
//   mode 0: y = acc + bias[col]
//   mode 1: y = 1 + softplus(acc + bias[col])
//   mode 2: y = sigmoid(acc + bias[col])
// fused=0: mode 3: y = compete[row*N+col] * silu(acc)
#define BM 128
#define BN 128
#define BK 16
#define LDW 20    // smem row stride in words (80B): conflict-free for LDSM & STS.128

__global__ void __launch_bounds__(256, 2)
gemm_tf32_kernel(const float* __restrict__ A,
                 const float* __restrict__ W0, const float* __restrict__ W1,
                 const float* __restrict__ W2,
                 const float* __restrict__ bias0, const float* __restrict__ bias1,
                 const float* __restrict__ bias2,
                 const float* __restrict__ comp,
                 float* __restrict__ C0, float* __restrict__ C1, float* __restrict__ C2,
                 int fused)
{
    __shared__ uint32_t As[2][BM][LDW];
    __shared__ uint32_t Bs[2][BN][LDW];

    const int K = DIM, N = DIM;

    int mode, ntile;
    const float* W;
    const float* bias;
    float* C;
    if (fused) {
        int wsel = blockIdx.x >> 3;
        ntile = blockIdx.x & 7;
        mode = wsel;
        W    = (wsel == 0) ? W0 : ((wsel == 1) ? W1 : W2);
        bias = (wsel == 0) ? bias0 : ((wsel == 1) ? bias1 : bias2);
        C    = (wsel == 0) ? C0 : ((wsel == 1) ? C1 : C2);
    } else {
        mode = 3; ntile = blockIdx.x; W = W0; bias = bias0; C = C0;
    }

    const int tid  = threadIdx.x;
    const int lane = tid & 31;
    const int warp = tid >> 5;
    const int warpM = warp >> 2;   // 0..1
    const int warpN = warp & 3;    // 0..3
    const int wmBase = warpM * 64;
    const int wnBase = warpN * 32;

    const int m0 = blockIdx.y * BM;
    const int n0 = ntile * BN;

    const int ldRow = tid >> 2;
    const int ldCol = (tid & 3) * 4;

    const float* Aptr  = A + (size_t)(m0 + ldRow) * K + ldCol;
    const float* Aptr2 = Aptr + (size_t)64 * K;
    const float* Wptr  = W + (size_t)(n0 + ldRow) * K + ldCol;
    const float* Wptr2 = Wptr + (size_t)64 * K;

    // ldmatrix per-thread source row/col within a 16x8 tf32 tile
    const int lRow = (lane & 7) + ((lane >> 3) & 1) * 8;  // 0..15
    const int lK   = (lane >> 4) * 4;                     // 0 or 4

    const uint32_t AsBase = smem_u32(&As[0][0][0]);
    const uint32_t BsBase = smem_u32(&Bs[0][0][0]);
    // byte address of this thread's ldmatrix row for A-tile mt in buffer buf at k-chunk kk:
    //   AsBase + ((buf*BM + wmBase + mt*16 + lRow)*LDW + kk + lK)*4

    float acc[4][4][4];
#pragma unroll
    for (int i = 0; i < 4; i++)
#pragma unroll
        for (int j = 0; j < 4; j++)
#pragma unroll
            for (int r = 0; r < 4; r++) acc[i][j][r] = 0.f;

    const int grp = lane >> 2;   // 0..7
    const int tig = lane & 3;    // 0..3

    // ---- prologue: stage k0=0 into buffer 0 ----
    float4 ra0 = *(const float4*)(Aptr);
    float4 ra1 = *(const float4*)(Aptr2);
    float4 rb0 = *(const float4*)(Wptr);
    float4 rb1 = *(const float4*)(Wptr2);
    {
        uint4 v;
        v.x = f2tf32(ra0.x); v.y = f2tf32(ra0.y); v.z = f2tf32(ra0.z); v.w = f2tf32(ra0.w);
        *(uint4*)&As[0][ldRow][ldCol] = v;
        v.x = f2tf32(ra1.x); v.y = f2tf32(ra1.y); v.z = f2tf32(ra1.z); v.w = f2tf32(ra1.w);
        *(uint4*)&As[0][ldRow + 64][ldCol] = v;
        v.x = f2tf32(rb0.x); v.y = f2tf32(rb0.y); v.z = f2tf32(rb0.z); v.w = f2tf32(rb0.w);
        *(uint4*)&Bs[0][ldRow][ldCol] = v;
        v.x = f2tf32(rb1.x); v.y = f2tf32(rb1.y); v.z = f2tf32(rb1.z); v.w = f2tf32(rb1.w);
        *(uint4*)&Bs[0][ldRow + 64][ldCol] = v;
    }
    __syncthreads();

    int cur = 0;
    for (int k0 = 0; k0 < K; k0 += BK) {
        const bool has_next = (k0 + BK) < K;
        if (has_next) {
            int kn = k0 + BK;
            ra0 = *(const float4*)(Aptr  + kn);
            ra1 = *(const float4*)(Aptr2 + kn);
            rb0 = *(const float4*)(Wptr  + kn);
            rb1 = *(const float4*)(Wptr2 + kn);
        }

        // ---- compute on buffer `cur` via ldmatrix ----
        const uint32_t aRow = (uint32_t)(cur * BM + wmBase + lRow) * (LDW * 4);
        const uint32_t bRow = (uint32_t)(cur * BN + wnBase + lRow) * (LDW * 4);
#pragma unroll
        for (int kk = 0; kk < BK; kk += 8) {
            const uint32_t kOff = (uint32_t)(kk + lK) * 4;
            uint32_t af[4][4];
#pragma unroll
            for (int mt = 0; mt < 4; mt++) {
                uint32_t addr = AsBase + aRow + (uint32_t)(mt * 16) * (LDW * 4) + kOff;
                ldsm_x4(af[mt][0], af[mt][1], af[mt][2], af[mt][3], addr);
            }
            uint32_t bf[4][2];
#pragma unroll
            for (int pr = 0; pr < 2; pr++) {
                uint32_t addr = BsBase + bRow + (uint32_t)(pr * 16) * (LDW * 4) + kOff;
                // x4 order: (n0-7,k0-3)->t0 reg0, (n8-15,k0-3)->t1 reg0,
                //           (n0-7,k4-7)->t0 reg1, (n8-15,k4-7)->t1 reg1
                ldsm_x4(bf[2 * pr][0], bf[2 * pr + 1][0], bf[2 * pr][1], bf[2 * pr + 1][1], addr);
            }
#pragma unroll
            for (int mt = 0; mt < 4; mt++)
#pragma unroll
                for (int nt = 0; nt < 4; nt++)
                    mma_tf32(acc[mt][nt], af[mt], bf[nt]);
        }

        if (has_next) {
            int nxt = cur ^ 1;
            uint4 v;
            v.x = f2tf32(ra0.x); v.y = f2tf32(ra0.y); v.z = f2tf32(ra0.z); v.w = f2tf32(ra0.w);
            *(uint4*)&As[nxt][ldRow][ldCol] = v;
            v.x = f2tf32(ra1.x); v.y = f2tf32(ra1.y); v.z = f2tf32(ra1.z); v.w = f2tf32(ra1.w);
            *(uint4*)&As[nxt][ldRow + 64][ldCol] = v;
            v.x = f2tf32(rb0.x); v.y = f2tf32(rb0.y); v.z = f2tf32(rb0.z); v.w = f2tf32(rb0.w);
            *(uint4*)&Bs[nxt][ldRow][ldCol] = v;
            v.x = f2tf32(rb1.x); v.y = f2tf32(rb1.y); v.z = f2tf32(rb1.z); v.w = f2tf32(rb1.w);
            *(uint4*)&Bs[nxt][ldRow + 64][ldCol] = v;
        }
        __syncthreads();
        cur ^= 1;
    }

    // ---- epilogue (float2 stores: reg pairs are adjacent columns) ----
#pragma unroll
    for (int mt = 0; mt < 4; mt++) {
#pragma unroll
        for (int nt = 0; nt < 4; nt++) {
#pragma unroll
            for (int half = 0; half < 2; half++) {
                int row = m0 + wmBase + mt * 16 + grp + half * 8;
                int col = n0 + wnBase + nt * 8 + 2 * tig;
                float v0 = acc[mt][nt][half * 2 + 0];
                float v1 = acc[mt][nt][half * 2 + 1];
                float y0, y1;
                if (mode == 0) {
                    y0 = v0 + bias[col]; y1 = v1 + bias[col + 1];
                } else if (mode == 1) {
                    float x0 = v0 + bias[col], x1 = v1 + bias[col + 1];
                    y0 = 1.0f + ((x0 > 20.f) ? x0 : log1pf(__expf(x0)));
                    y1 = 1.0f + ((x1 > 20.f) ? x1 : log1pf(__expf(x1)));
                } else if (mode == 2) {
                    float x0 = v0 + bias[col], x1 = v1 + bias[col + 1];
                    y0 = 1.0f / (1.0f + __expf(-x0));
                    y1 = 1.0f / (1.0f + __expf(-x1));
                } else {
                    float s0 = v0 / (1.0f + __expf(-v0));
                    float s1 = v1 / (1.0f + __expf(-v1));
                    const float2 cc = *(const float2*)(comp + (size_t)row * N + col);
                    y0 = cc.x * s0; y1 = cc.y * s1;
                }
                float2 o; o.x = y0; o.y = y1;
                *(float2*)(C + (size_t)row * N + col) = o;
            }
        }
    }
}

// ---------------- sequential scan (elementwise recurrence only) ----------------
__global__ void __launch_bounds__(128)
scan_kernel(const float* __restrict__ vx, const float* __restrict__ alpha,
            const float* __restrict__ delta, const float* __restrict__ h0,
            const float* __restrict__ r_h, float* __restrict__ out_h)
{
    int gtid = blockIdx.x * 128 + threadIdx.x;   // 0..16383
    int b = gtid >> 10;            // /DIM
    int d = gtid & 1023;
    size_t base = (size_t)b * DIM + d;

    float rh = r_h[d];
    float h = h0[base];
    out_h[base] = h;               // h[0] = h0

    const int S = BD;              // stride per timestep
    float pvx[8], pal[8], pdl[8];
#pragma unroll
    for (int i = 0; i < 8; i++) {
        size_t off = (size_t)i * S + base;
        pvx[i] = __ldcs(vx + off);
        pal[i] = __ldcs(alpha + off);
        pdl[i] = __ldcs(delta + off);
    }

    for (int t0 = 0; t0 < TT; t0 += 8) {
#pragma unroll
        for (int i = 0; i < 8; i++) {
            int t = t0 + i;
            float vv = pvx[i], aa = pal[i], dd = pdl[i];
            int tn = t + 8;
            if (tn < TT) {
                size_t off = (size_t)tn * S + base;
                pvx[i] = __ldcs(vx + off);
                pal[i] = __ldcs(alpha + off);
                pdl[i] = __ldcs(delta + off);
            }
            float v = vv + rh * h;
            float av = fminf(fmaxf(fabsf(v), 1e-6f), 10.0f);
            float cand = __powf(av, aa);
            cand = (v >= 0.f) ? cand : -cand;
            if (v == 0.f) cand = 0.f;     // jnp.sign(0) == 0
            h = h + dd * (cand - h);
            out_h[(size_t)(t + 1) * S + base] = h;
        }
    }
}

// ---------------- compete = group softmax over h[1:], fully parallel ----------------
__global__ void __launch_bounds__(256)
compete_kernel(const float* __restrict__ h, float* __restrict__ comp)
{
    size_t idx = (size_t)blockIdx.x * blockDim.x + threadIdx.x;
    float v = h[idx];
    float m = v;
#pragma unroll
    for (int o = 16; o > 0; o >>= 1) m = fmaxf(m, __shfl_xor_sync(0xffffffffu, m, o));
    float e = __expf(v - m);
    float s = e;
#pragma unroll
    for (int o = 16; o > 0; o >>= 1) s += __shfl_xor_sync(0xffffffffu, s, o);
    comp[idx] = e / s;
}

// ---------------- launch ----------------
extern "C" void kernel_launch(void* const* d_in, const int* in_sizes, int n_in,
                              void* d_out, int out_size)
{
    const float* x       = (const float*)d_in[0];   // [T,B,D]
    const float* h0      = (const float*)d_in[1];   // [B,D]
    const float* W_x     = (const float*)d_in[2];   // [D,D]
    const float* r_h     = (const float*)d_in[3];   // [D]
    const float* b       = (const float*)d_in[4];   // [D]
    const float* W_alpha = (const float*)d_in[5];
    const float* b_alpha = (const float*)d_in[6];
    const float* W_delta = (const float*)d_in[7];
    const float* b_delta = (const float*)d_in[8];
    const float* W_out   = (const float*)d_in[9];

    float* out = (float*)d_out;
    float* out_h = out;                                  // [T+1,B,D]
    float* out_y = out + (size_t)(TT + 1) * BD;          // [T,B,D]

    float *vx, *al, *dl, *cp;
    cudaGetSymbolAddress((void**)&vx, g_vx);
    cudaGetSymbolAddress((void**)&al, g_alpha);
    cudaGetSymbolAddress((void**)&dl, g_delta);
    cudaGetSymbolAddress((void**)&cp, g_compete);

    // 1) fused projections: one launch, 3 weights (A tile L2-shared across weights)
    dim3 pgrid(3 * (DIM / BN), MROWS / BM);   // (24, 128)
    gemm_tf32_kernel<<<pgrid, 256>>>(x, W_x, W_alpha, W_delta, b, b_alpha, b_delta,
                                     nullptr, vx, al, dl, 1);
    // 2) sequential scan -> h states (written straight into d_out)
    scan_kernel<<<128, 128>>>(vx, al, dl, h0, r_h, out_h);
    // 3) group softmax over h[1:]
    compete_kernel<<<(MROWS * DIM) / 256, 256>>>(out_h + BD, cp);
    // 4) output GEMM with compete*silu epilogue
    dim3 ogrid(DIM / BN, MROWS / BM);          // (8, 128)
    gemm_tf32_kernel<<<ogrid, 256>>>(out_h + BD, W_out, nullptr, nullptr,
                                     nullptr, nullptr, nullptr,
                                     cp, out_y, nullptr, nullptr, 0);
}